// round 1
// baseline (speedup 1.0000x reference)
#include <cuda_runtime.h>
#include <math.h>

#define NN 2048
#define CC 64
#define JT 256      // j-threads per block
#define ICH 32      // i rows per block

// ---- device scratch (no allocations allowed) ----
__device__ float4 g_pos[NN];    // x, y, z, s0
__device__ float4 g_miscI[NN];  // w0, exp(-rA_hi), exp(-dA_hi), pad   (i-side)
__device__ float4 g_miscJ[NN];  // w0, exp(-rB_lo), exp(-dB_lo), pad   (j-side)
__device__ double g_acc;

__device__ __forceinline__ float sqrt_approx(float x) {
    float r; asm("sqrt.approx.f32 %0, %1;" : "=f"(r) : "f"(x)); return r;
}
__device__ __forceinline__ float rcp_approx(float x) {
    float r; asm("rcp.approx.f32 %0, %1;" : "=f"(r) : "f"(x)); return r;
}

__global__ void zero_kernel() { g_acc = 0.0; }

// One thread per node: 4 dot products (len 64) + 4 exps.
__global__ void pre_kernel(const float* __restrict__ X,
                           const float* __restrict__ embs,
                           const float* __restrict__ w0,
                           const float* __restrict__ s0,
                           const float* __restrict__ df,
                           const float* __restrict__ rf) {
    int n = blockIdx.x * blockDim.x + threadIdx.x;
    if (n >= NN) return;
    const float* e = embs + n * CC;
    float drl = 0.f, drh = 0.f, ddl = 0.f, ddh = 0.f;
#pragma unroll 8
    for (int c = 0; c < CC; c++) {
        float v = e[c];
        drl = fmaf(v, __ldg(rf + c),      drl);   // radius_factor[:C]  -> j axis
        drh = fmaf(v, __ldg(rf + CC + c), drh);   // radius_factor[C:]  -> i axis
        ddl = fmaf(v, __ldg(df + c),      ddl);
        ddh = fmaf(v, __ldg(df + CC + c), ddh);
    }
    g_pos[n]   = make_float4(X[n * 3], X[n * 3 + 1], X[n * 3 + 2], s0[n]);
    g_miscI[n] = make_float4(w0[n], __expf(-drh), __expf(-ddh), 0.f);
    g_miscJ[n] = make_float4(w0[n], __expf(-drl), __expf(-ddl), 0.f);
}

// Pairwise energy. Block: 256 threads cover 256 consecutive j; loop over ICH i-rows.
__global__ void __launch_bounds__(JT) pair_kernel(const float* __restrict__ mask) {
    const int j  = blockIdx.x * JT + threadIdx.x;
    const int i0 = blockIdx.y * ICH;

    const float4 pj = g_pos[j];
    const float4 mj = g_miscJ[j];

    float acc = 0.f;
#pragma unroll 4
    for (int k = 0; k < ICH; k++) {
        const int i = i0 + k;
        const float4 pi = g_pos[i];
        const float4 mi = g_miscI[i];

        const float m = __ldg(mask + (size_t)i * NN + j);

        const float dx = pj.x - pi.x;
        const float dy = pj.y - pi.y;
        const float dz = pj.z - pi.z;
        const float r2 = fmaf(dx, dx, fmaf(dy, dy, fmaf(dz, dz, 3e-6f)));
        const float D  = sqrt_approx(r2);

        // sigmoids via precomputed per-node exps
        const float sr = rcp_approx(fmaf(mi.y, mj.y, 1.f));  // sigmoid(rA_i + rB_j)
        const float sd = rcp_approx(fmaf(mi.z, mj.z, 1.f));  // sigmoid(dA_i + dB_j)

        const float s  = (pi.w + pj.w) * fmaf(0.8f, sr, 0.4f);
        const float Dm = D - s;

        // attr = (exp(-(Dm-.3)^2) + exp(-3 Dm^2) + exp(-10 Dm^2)) / 3
        //      = (t*u + t^3 + t^10)/3  with t = exp(-Dm^2), u = exp(0.6 Dm - 0.09)
        const float t  = __expf(-Dm * Dm);
        const float u  = __expf(fmaf(0.6f, Dm, -0.09f));
        const float t2 = t * t;
        const float t3 = t2 * t;
        const float t4 = t2 * t2;
        const float t8 = t4 * t4;
        const float t10 = t8 * t2;
        const float attr3 = fmaf(t, u, t3 + t10);

        const float w = sqrt_approx(fmaf(mi.x, mj.x, 1e-6f)) * (sd + 0.5f);

        // repl = 5 * exp(-0.3 D^3);  D^3 = D * r2
        const float repl = 5.f * __expf(-0.3f * D * r2);

        // contribution: mask * (repl - w * attr3 / 3)
        acc += m * fmaf(-w * (1.f / 3.f), attr3, repl);
    }

    // block reduction
    __shared__ float sred[JT];
    sred[threadIdx.x] = acc;
    __syncthreads();
#pragma unroll
    for (int off = JT / 2; off >= 32; off >>= 1) {
        if (threadIdx.x < off) sred[threadIdx.x] += sred[threadIdx.x + off];
        __syncthreads();
    }
    if (threadIdx.x < 32) {
        float v = sred[threadIdx.x];
#pragma unroll
        for (int off = 16; off > 0; off >>= 1)
            v += __shfl_down_sync(0xFFFFFFFFu, v, off);
        if (threadIdx.x == 0) atomicAdd(&g_acc, (double)v);
    }
}

__global__ void fin_kernel(float* out) {
    float v = (float)g_acc;
    out[0] = isnan(v) ? 1e-6f : v;
}

extern "C" void kernel_launch(void* const* d_in, const int* in_sizes, int n_in,
                              void* d_out, int out_size) {
    const float* X    = (const float*)d_in[0];  // (1, N, 3)
    const float* embs = (const float*)d_in[1];  // (1, N, C)
    const float* w0   = (const float*)d_in[2];  // (N,)
    const float* s0   = (const float*)d_in[3];  // (N,)
    const float* mask = (const float*)d_in[4];  // (1, N, N)
    const float* df   = (const float*)d_in[5];  // (2C, 1)
    const float* rf   = (const float*)d_in[6];  // (2C, 1)
    float* out = (float*)d_out;

    zero_kernel<<<1, 1>>>();
    pre_kernel<<<(NN + 255) / 256, 256>>>(X, embs, w0, s0, df, rf);
    dim3 grid(NN / JT, NN / ICH);   // 8 x 64 = 512 blocks
    pair_kernel<<<grid, JT>>>(mask);
    fin_kernel<<<1, 1>>>(out);
}

// round 2
// speedup vs baseline: 1.5203x; 1.5203x over previous
#include <cuda_runtime.h>
#include <math.h>

#define NN  2048
#define CC  64
#define NT  256     // j-threads per block
#define ICH 32      // i rows per block
#define GX  (NN / NT)    // 8
#define GY  (NN / ICH)   // 64
#define NBLK (GX * GY)   // 512

__device__ double   g_acc;    // zero-init at load; reset by last block each run
__device__ unsigned g_count;  // zero-init at load; reset by last block each run

__device__ __forceinline__ float sqrt_approx(float x) {
    float r; asm("sqrt.approx.f32 %0, %1;" : "=f"(r) : "f"(x)); return r;
}
__device__ __forceinline__ float rcp_approx(float x) {
    float r; asm("rcp.approx.f32 %0, %1;" : "=f"(r) : "f"(x)); return r;
}

__global__ void __launch_bounds__(NT) fused_kernel(
    const float* __restrict__ X,     // (N,3)
    const float* __restrict__ embs,  // (N,C)
    const float* __restrict__ w0,    // (N,)
    const float* __restrict__ s0,    // (N,)
    const float* __restrict__ mask,  // (N,N)
    const float* __restrict__ df,    // (2C,)
    const float* __restrict__ rf,    // (2C,)
    float* __restrict__ out)
{
    const int tid = threadIdx.x;
    const int j   = blockIdx.x * NT + tid;
    const int i0  = blockIdx.y * ICH;

    __shared__ float4 sPosI[ICH];   // x,y,z,s0
    __shared__ float4 sMiscI[ICH];  // w0, exp(-r_hi), exp(-d_hi), pad
    __shared__ float  sred[NT];

    // ---- phase A: per-node precompute ----
    // j-side (every thread, its own j): dots against the LOW halves of rf/df
    float rlo = 0.f, dlo = 0.f;
    {
        const float4* ej = (const float4*)(embs + (size_t)j * CC);
#pragma unroll
        for (int c = 0; c < CC / 4; c++) {
            const float4 v = ej[c];
            rlo = fmaf(v.x, __ldg(rf + 4*c + 0), rlo);
            rlo = fmaf(v.y, __ldg(rf + 4*c + 1), rlo);
            rlo = fmaf(v.z, __ldg(rf + 4*c + 2), rlo);
            rlo = fmaf(v.w, __ldg(rf + 4*c + 3), rlo);
            dlo = fmaf(v.x, __ldg(df + 4*c + 0), dlo);
            dlo = fmaf(v.y, __ldg(df + 4*c + 1), dlo);
            dlo = fmaf(v.z, __ldg(df + 4*c + 2), dlo);
            dlo = fmaf(v.w, __ldg(df + 4*c + 3), dlo);
        }
    }
    const float xj = X[3*j], yj = X[3*j+1], zj = X[3*j+2];
    const float s0j = s0[j], w0j = w0[j];
    const float eRj = __expf(-rlo);   // exp(-rB_lo[j])
    const float eDj = __expf(-dlo);

    // i-side (threads 0..31): dots against the HIGH halves of rf/df
    if (tid < ICH) {
        const int i = i0 + tid;
        const float4* ei = (const float4*)(embs + (size_t)i * CC);
        float rhi = 0.f, dhi = 0.f;
#pragma unroll
        for (int c = 0; c < CC / 4; c++) {
            const float4 v = ei[c];
            rhi = fmaf(v.x, __ldg(rf + CC + 4*c + 0), rhi);
            rhi = fmaf(v.y, __ldg(rf + CC + 4*c + 1), rhi);
            rhi = fmaf(v.z, __ldg(rf + CC + 4*c + 2), rhi);
            rhi = fmaf(v.w, __ldg(rf + CC + 4*c + 3), rhi);
            dhi = fmaf(v.x, __ldg(df + CC + 4*c + 0), dhi);
            dhi = fmaf(v.y, __ldg(df + CC + 4*c + 1), dhi);
            dhi = fmaf(v.z, __ldg(df + CC + 4*c + 2), dhi);
            dhi = fmaf(v.w, __ldg(df + CC + 4*c + 3), dhi);
        }
        sPosI[tid]  = make_float4(X[3*i], X[3*i+1], X[3*i+2], s0[i]);
        sMiscI[tid] = make_float4(w0[i], __expf(-rhi), __expf(-dhi), 0.f);
    }
    __syncthreads();

    // ---- phase B: pairwise energy ----
    float acc = 0.f;
#pragma unroll 4
    for (int k = 0; k < ICH; k++) {
        const float4 pi = sPosI[k];
        const float4 mi = sMiscI[k];
        const float  m  = __ldg(mask + (size_t)(i0 + k) * NN + j);

        const float dx = xj - pi.x;
        const float dy = yj - pi.y;
        const float dz = zj - pi.z;
        const float r2 = fmaf(dx, dx, fmaf(dy, dy, fmaf(dz, dz, 3e-6f)));
        const float D  = sqrt_approx(r2);

        // sigmoid(a_i + b_j) = 1 / (1 + exp(-a_i)*exp(-b_j))
        const float sr = rcp_approx(fmaf(mi.y, eRj, 1.f));
        const float sd = rcp_approx(fmaf(mi.z, eDj, 1.f));

        const float s  = (pi.w + s0j) * fmaf(0.8f, sr, 0.4f);
        const float Dm = D - s;

        // attr*3 = exp(-(Dm-.3)^2) + t^3 + t^10, with t = exp(-Dm^2),
        //          exp(-(Dm-.3)^2) = t * exp(0.6 Dm - 0.09)
        const float t   = __expf(-Dm * Dm);
        const float u   = __expf(fmaf(0.6f, Dm, -0.09f));
        const float t2  = t * t;
        const float t3  = t2 * t;
        const float t4  = t2 * t2;
        const float t8  = t4 * t4;
        const float t10 = t8 * t2;
        const float attr3 = fmaf(t, u, t3 + t10);

        const float w = sqrt_approx(fmaf(mi.x, w0j, 1e-6f)) * (sd + 0.5f);

        // repl = 5 * exp(-0.3 * D^3);  D^3 = D * r2
        const float repl = 5.f * __expf(-0.3f * D * r2);

        acc += m * fmaf(-w * (1.f / 3.f), attr3, repl);
    }

    // ---- block reduction ----
    sred[tid] = acc;
    __syncthreads();
#pragma unroll
    for (int off = NT / 2; off >= 32; off >>= 1) {
        if (tid < off) sred[tid] += sred[tid + off];
        __syncthreads();
    }
    if (tid < 32) {
        float v = sred[tid];
#pragma unroll
        for (int off = 16; off > 0; off >>= 1)
            v += __shfl_down_sync(0xFFFFFFFFu, v, off);

        if (tid == 0) {
            atomicAdd(&g_acc, (double)v);
            __threadfence();
            const unsigned prev = atomicAdd(&g_count, 1u);
            if (prev == NBLK - 1) {
                // all blocks' g_acc adds are visible (fence before counter add)
                __threadfence();
                const float r = (float)g_acc;
                out[0] = isnan(r) ? 1e-6f : r;
                // reset state for the next (graph-replayed) invocation
                g_acc   = 0.0;
                g_count = 0u;
            }
        }
    }
}

extern "C" void kernel_launch(void* const* d_in, const int* in_sizes, int n_in,
                              void* d_out, int out_size) {
    const float* X    = (const float*)d_in[0];  // (1, N, 3)
    const float* embs = (const float*)d_in[1];  // (1, N, C)
    const float* w0   = (const float*)d_in[2];  // (N,)
    const float* s0   = (const float*)d_in[3];  // (N,)
    const float* mask = (const float*)d_in[4];  // (1, N, N)
    const float* df   = (const float*)d_in[5];  // (2C, 1)
    const float* rf   = (const float*)d_in[6];  // (2C, 1)
    float* out = (float*)d_out;

    dim3 grid(GX, GY);   // 8 x 64 = 512 blocks
    fused_kernel<<<grid, NT>>>(X, embs, w0, s0, mask, df, rf, out);
}